// round 7
// baseline (speedup 1.0000x reference)
#include <cuda_runtime.h>

#define NMAX 100000
#define EMAX 1600000

// ---------------- scratch (device globals: no allocs allowed) ----------------
__device__ float g_h1 [NMAX * 64];
__device__ float g_h1o[NMAX * 64];
__device__ float g_h2 [NMAX * 64];
__device__ float g_es1[NMAX * 8];
__device__ float g_ed1[NMAX * 8];
__device__ float g_es2[NMAX];
__device__ float g_ed2[NMAX];
__device__ int   g_deg[NMAX];
__device__ int   g_cur[NMAX];
__device__ int   g_rowptr[NMAX + 1];
__device__ int   g_csrc[EMAX];
__device__ int   g_is64;

typedef unsigned long long u64;

__device__ __forceinline__ u64 pack2(float lo, float hi) {
    u64 r; asm("mov.b64 %0, {%1, %2};" : "=l"(r) : "f"(lo), "f"(hi)); return r;
}
__device__ __forceinline__ void unpack2(u64 v, float& lo, float& hi) {
    asm("mov.b64 {%0, %1}, %2;" : "=f"(lo), "=f"(hi) : "l"(v));
}
__device__ __forceinline__ u64 ffma2(u64 a, u64 b, u64 c) {
    u64 d; asm("fma.rn.f32x2 %0, %1, %2, %3;" : "=l"(d) : "l"(a), "l"(b), "l"(c)); return d;
}
__device__ __forceinline__ float lrelu(float t) { return t > 0.f ? t : 0.2f * t; }

// ---------------- edge dtype probe: int64 buffers have zero odd words ----------------
__global__ void detect_kernel(const int* __restrict__ ei) {
    if (threadIdx.x == 0 && blockIdx.x == 0) {
        int all_zero = 1;
        for (int i = 1; i < 64; i += 2)
            if (ei[i] != 0) all_zero = 0;
        g_is64 = all_zero;
    }
}

// decode src/dst of edge e from a buffer that is either int32[2E] or int64[2E]
__device__ __forceinline__ int edge_dst(const int* ei, int E, int e) {
    return g_is64 ? ei[2 * (E + e)] : ei[E + e];
}
__device__ __forceinline__ int edge_src(const int* ei, int E, int e) {
    return g_is64 ? ei[2 * e] : ei[e];
}

// ---------------- CSR build (dst-sorted), int atomics only ----------------
__global__ void count_kernel(const int* __restrict__ ei, int E, int N) {
    int e = blockIdx.x * blockDim.x + threadIdx.x;
    if (e < E) {
        int dst = edge_dst(ei, E, e);
        if ((unsigned)dst < (unsigned)N) atomicAdd(&g_deg[dst], 1);
    }
}

__global__ void scan_kernel(int N) {
    __shared__ int ps[1024];
    int t = threadIdx.x;
    int chunk = (N + 1023) >> 10;
    int start = t * chunk;
    int end = start + chunk; if (end > N) end = N; if (start > N) start = N;
    int s = 0;
    for (int i = start; i < end; i++) s += g_deg[i];
    ps[t] = s;
    __syncthreads();
    for (int off = 1; off < 1024; off <<= 1) {
        int v = (t >= off) ? ps[t - off] : 0;
        __syncthreads();
        ps[t] += v;
        __syncthreads();
    }
    int run = ps[t] - s;                 // exclusive prefix
    for (int i = start; i < end; i++) { g_rowptr[i] = run; run += g_deg[i]; }
    if (t == 1023) g_rowptr[N] = ps[1023];
}

__global__ void scatter_kernel(const int* __restrict__ ei, int E, int N) {
    int e = blockIdx.x * blockDim.x + threadIdx.x;
    if (e < E) {
        int dst = edge_dst(ei, E, e);
        int src = edge_src(ei, E, e);
        if ((unsigned)dst >= (unsigned)N) return;
        int pos = g_rowptr[dst] + atomicAdd(&g_cur[dst], 1);
        if ((unsigned)pos < (unsigned)EMAX) g_csrc[pos] = src;
    }
}

// ---------------- GEMM: H[N,64] = X[N,K] @ W[K,64]  (f32x2, k-pair packed) ----------------
template <int K>
__global__ __launch_bounds__(128)
void gemm_kernel(const float* __restrict__ X, const float* __restrict__ W,
                 float* __restrict__ H, int N)
{
    constexpr int KT = 64;
    __shared__ __align__(16) float xs[32][KT];     // 8 KB
    __shared__ u64 ws2[KT / 2][64];                // 16 KB: (W[k],W[k+1]) pairs per col
    const int n0   = blockIdx.x * 32;
    const int cb   = threadIdx.x & 31;             // cols cb and cb+32
    const int slot = threadIdx.x >> 5;             // 4 slots x 8 nodes

    u64 accA[8], accB[8];
#pragma unroll
    for (int j = 0; j < 8; j++) { accA[j] = 0ull; accB[j] = 0ull; }

    for (int k0 = 0; k0 < K; k0 += KT) {
        const int len = (K - k0 < KT) ? (K - k0) : KT;   // always even (300, 64)
        for (int i = threadIdx.x; i < 32 * len; i += 128) {
            int r = i / len, c = i - r * len;
            int n = n0 + r;
            xs[r][c] = (n < N) ? X[(size_t)n * K + k0 + c] : 0.f;
        }
        for (int i = threadIdx.x; i < (len / 2) * 64; i += 128) {
            int kk2 = i >> 6, c = i & 63;
            float w0 = W[(size_t)(k0 + 2 * kk2) * 64 + c];
            float w1 = W[(size_t)(k0 + 2 * kk2 + 1) * 64 + c];
            ws2[kk2][c] = pack2(w0, w1);
        }
        __syncthreads();
        const int len2 = len >> 1;
        for (int kk2 = 0; kk2 < len2; kk2++) {
            u64 wA = ws2[kk2][cb];
            u64 wB = ws2[kk2][cb + 32];
#pragma unroll
            for (int j = 0; j < 8; j++) {
                u64 x2 = *reinterpret_cast<const u64*>(&xs[slot * 8 + j][kk2 * 2]);
                accA[j] = ffma2(x2, wA, accA[j]);
                accB[j] = ffma2(x2, wB, accB[j]);
            }
        }
        __syncthreads();
    }
#pragma unroll
    for (int j = 0; j < 8; j++) {
        int n = n0 + slot * 8 + j;
        if (n < N) {
            float a0, a1, b0, b1;
            unpack2(accA[j], a0, a1);
            unpack2(accB[j], b0, b1);
            H[(size_t)n * 64 + cb]      = a0 + a1;
            H[(size_t)n * 64 + cb + 32] = b0 + b1;
        }
    }
}

// ---------------- per-node attention logits, layer 1 (8 heads x 8 dims) ----------------
__global__ void att1_kernel(const float* __restrict__ H,
                            const float* __restrict__ as, const float* __restrict__ ad, int N)
{
    int t = blockIdx.x * blockDim.x + threadIdx.x;
    if (t >= N * 8) return;
    int h = t & 7;
    const float4* hp = reinterpret_cast<const float4*>(H + (size_t)t * 8);  // n*64 + h*8 == t*8
    float4 v0 = hp[0], v1 = hp[1];
    const float4* ap = reinterpret_cast<const float4*>(as + h * 8);
    float4 a0 = ap[0], a1 = ap[1];
    g_es1[t] = v0.x * a0.x + v0.y * a0.y + v0.z * a0.z + v0.w * a0.w +
               v1.x * a1.x + v1.y * a1.y + v1.z * a1.z + v1.w * a1.w;
    const float4* bp = reinterpret_cast<const float4*>(ad + h * 8);
    float4 b0 = bp[0], b1 = bp[1];
    g_ed1[t] = v0.x * b0.x + v0.y * b0.y + v0.z * b0.z + v0.w * b0.w +
               v1.x * b1.x + v1.y * b1.y + v1.z * b1.z + v1.w * b1.w;
}

// ---------------- per-node attention logits, layer 2 (1 head x 64 dims) ----------------
__global__ void att2_kernel(const float* __restrict__ H,
                            const float* __restrict__ as, const float* __restrict__ ad, int N)
{
    int g = blockIdx.x * blockDim.x + threadIdx.x;
    int n = g >> 5, lane = g & 31;
    if (n >= N) return;
    float vA = H[(size_t)n * 64 + lane];
    float vB = H[(size_t)n * 64 + lane + 32];
    float s = vA * as[lane] + vB * as[lane + 32];
    float d = vA * ad[lane] + vB * ad[lane + 32];
#pragma unroll
    for (int o = 16; o; o >>= 1) {
        s += __shfl_xor_sync(0xffffffffu, s, o);
        d += __shfl_xor_sync(0xffffffffu, d, o);
    }
    if (lane == 0) { g_es2[n] = s; g_ed2[n] = d; }
}

// ---------------- layer-1 aggregation: fused softmax + gather + bias + ELU ----------------
// warp per node; lane covers cols (lane, lane+32) -> heads (lane>>3, lane>>3 + 4)
__global__ void agg1_kernel(const float* __restrict__ H, const float* __restrict__ bias,
                            float* __restrict__ O, int N)
{
    int g = blockIdx.x * blockDim.x + threadIdx.x;
    int n = g >> 5, lane = g & 31;
    if (n >= N) return;
    int hA = lane >> 3, hB = hA + 4;
    float edA = g_ed1[n * 8 + hA], edB = g_ed1[n * 8 + hB];

    // self-loop (PyG default add_self_loops)
    float wA = __expf(lrelu(g_es1[n * 8 + hA] + edA));
    float wB = __expf(lrelu(g_es1[n * 8 + hB] + edB));
    float wsA = wA, wsB = wB;
    float accA = wA * H[(size_t)n * 64 + lane];
    float accB = wB * H[(size_t)n * 64 + lane + 32];

    int e0 = g_rowptr[n], e1 = g_rowptr[n + 1];
    for (int e = e0; e < e1; e++) {
        int s = g_csrc[e];
        float xA = __expf(lrelu(g_es1[s * 8 + hA] + edA));
        float xB = __expf(lrelu(g_es1[s * 8 + hB] + edB));
        wsA += xA; wsB += xB;
        accA = fmaf(xA, H[(size_t)s * 64 + lane],      accA);
        accB = fmaf(xB, H[(size_t)s * 64 + lane + 32], accB);
    }
    float oA = accA / wsA + bias[lane];
    float oB = accB / wsB + bias[lane + 32];
    O[(size_t)n * 64 + lane]      = oA > 0.f ? oA : (__expf(oA) - 1.f);  // ELU
    O[(size_t)n * 64 + lane + 32] = oB > 0.f ? oB : (__expf(oB) - 1.f);
}

// ---------------- layer-2 aggregation + bias + log_softmax -> d_out ----------------
__global__ void agg2_kernel(const float* __restrict__ H, const float* __restrict__ bias,
                            float* __restrict__ O, int N)
{
    int g = blockIdx.x * blockDim.x + threadIdx.x;
    int n = g >> 5, lane = g & 31;
    if (n >= N) return;
    float edn = g_ed2[n];

    float w  = __expf(lrelu(g_es2[n] + edn));   // self-loop
    float ws = w;
    float accA = w * H[(size_t)n * 64 + lane];
    float accB = w * H[(size_t)n * 64 + lane + 32];

    int e0 = g_rowptr[n], e1 = g_rowptr[n + 1];
    for (int e = e0; e < e1; e++) {
        int s = g_csrc[e];
        float x = __expf(lrelu(g_es2[s] + edn));
        ws += x;
        accA = fmaf(x, H[(size_t)s * 64 + lane],      accA);
        accB = fmaf(x, H[(size_t)s * 64 + lane + 32], accB);
    }
    float vA = accA / ws + bias[lane];
    float vB = accB / ws + bias[lane + 32];

    // log_softmax over the 64 columns (2 per lane)
    float mx = fmaxf(vA, vB);
#pragma unroll
    for (int o = 16; o; o >>= 1) mx = fmaxf(mx, __shfl_xor_sync(0xffffffffu, mx, o));
    float se = __expf(vA - mx) + __expf(vB - mx);
#pragma unroll
    for (int o = 16; o; o >>= 1) se += __shfl_xor_sync(0xffffffffu, se, o);
    float lse = mx + logf(se);
    O[(size_t)n * 64 + lane]      = vA - lse;
    O[(size_t)n * 64 + lane + 32] = vB - lse;
}

// ---------------- launch ----------------
extern "C" void kernel_launch(void* const* d_in, const int* in_sizes, int n_in,
                              void* d_out, int out_size)
{
    const float* x   = (const float*)d_in[0];
    const int*   ei  = (const int*)d_in[1];    // int32 OR int64 (probed on device)
    const float* W1  = (const float*)d_in[2];
    const float* as1 = (const float*)d_in[3];
    const float* ad1 = (const float*)d_in[4];
    const float* b1  = (const float*)d_in[5];
    const float* W2  = (const float*)d_in[6];
    const float* as2 = (const float*)d_in[7];
    const float* ad2 = (const float*)d_in[8];
    const float* b2  = (const float*)d_in[9];

    const int N = in_sizes[0] / 300;
    const int E = in_sizes[1] / 2;   // logical edge count under both dtypes
    float* out = (float*)d_out;

    void *pdeg, *pcur, *ph1, *ph1o, *ph2;
    cudaGetSymbolAddress(&pdeg, g_deg);
    cudaGetSymbolAddress(&pcur, g_cur);
    cudaGetSymbolAddress(&ph1,  g_h1);
    cudaGetSymbolAddress(&ph1o, g_h1o);
    cudaGetSymbolAddress(&ph2,  g_h2);
    float* h1  = (float*)ph1;
    float* h1o = (float*)ph1o;
    float* h2  = (float*)ph2;

    const int tb = 256;

    // CSR build (dst buckets), reused by both layers
    cudaMemsetAsync(pdeg, 0, N * sizeof(int), 0);
    cudaMemsetAsync(pcur, 0, N * sizeof(int), 0);
    detect_kernel <<<1, 32>>>(ei);
    count_kernel  <<<(E + tb - 1) / tb, tb>>>(ei, E, N);
    scan_kernel   <<<1, 1024>>>(N);
    scatter_kernel<<<(E + tb - 1) / tb, tb>>>(ei, E, N);

    // layer 1
    gemm_kernel<300><<<(N + 31) / 32, 128>>>(x, W1, h1, N);
    att1_kernel<<<(N * 8 + tb - 1) / tb, tb>>>(h1, as1, ad1, N);
    agg1_kernel<<<(N + 7) / 8, tb>>>(h1, b1, h1o, N);

    // layer 2
    gemm_kernel<64><<<(N + 31) / 32, 128>>>(h1o, W2, h2, N);
    att2_kernel<<<(N + 7) / 8, tb>>>(h2, as2, ad2, N);
    agg2_kernel<<<(N + 7) / 8, tb>>>(h2, b2, out, N);
}

// round 8
// speedup vs baseline: 1.0400x; 1.0400x over previous
#include <cuda_runtime.h>

#define NMAX 100000
#define EMAX 1600000

// ---------------- scratch (device globals: no allocs allowed) ----------------
__device__ float g_h1 [NMAX * 64];
__device__ float g_h1o[NMAX * 64];
__device__ float g_h2 [NMAX * 64];
__device__ float g_es1[NMAX * 8];
__device__ float g_ed1[NMAX * 8];
__device__ float g_es2[NMAX];
__device__ float g_ed2[NMAX];
__device__ int   g_deg[NMAX];
__device__ int   g_cur[NMAX];
__device__ int   g_rowptr[NMAX + 1];
__device__ int   g_csrc[EMAX];
__device__ int   g_is64;

typedef unsigned long long u64;

__device__ __forceinline__ u64 pack2(float lo, float hi) {
    u64 r; asm("mov.b64 %0, {%1, %2};" : "=l"(r) : "f"(lo), "f"(hi)); return r;
}
__device__ __forceinline__ void unpack2(u64 v, float& lo, float& hi) {
    asm("mov.b64 {%0, %1}, %2;" : "=f"(lo), "=f"(hi) : "l"(v));
}
__device__ __forceinline__ u64 ffma2(u64 a, u64 b, u64 c) {
    u64 d; asm("fma.rn.f32x2 %0, %1, %2, %3;" : "=l"(d) : "l"(a), "l"(b), "l"(c)); return d;
}
__device__ __forceinline__ float lrelu(float t) { return t > 0.f ? t : 0.2f * t; }

// ---------------- init: zero deg/cur + edge dtype probe (one launch) ----------------
__global__ void init_kernel(const int* __restrict__ ei, int N) {
    int i = blockIdx.x * blockDim.x + threadIdx.x;
    if (i < N) { g_deg[i] = 0; g_cur[i] = 0; }
    if (i == 0) {
        // little-endian int64 node ids (< 2^31) have zero odd 32-bit words
        int all_zero = 1;
        for (int k = 1; k < 64; k += 2)
            if (ei[k] != 0) all_zero = 0;
        g_is64 = all_zero;
    }
}

__device__ __forceinline__ int edge_dst(const int* ei, int E, int e) {
    return g_is64 ? ei[2 * (E + e)] : ei[E + e];
}
__device__ __forceinline__ int edge_src(const int* ei, int E, int e) {
    return g_is64 ? ei[2 * e] : ei[e];
}

// ---------------- CSR build (dst-sorted), int atomics only ----------------
__global__ void count_kernel(const int* __restrict__ ei, int E, int N) {
    int e = blockIdx.x * blockDim.x + threadIdx.x;
    if (e < E) {
        int dst = edge_dst(ei, E, e);
        if ((unsigned)dst < (unsigned)N) atomicAdd(&g_deg[dst], 1);
    }
}

__global__ void scan_kernel(int N) {
    __shared__ int ps[1024];
    int t = threadIdx.x;
    int chunk = (N + 1023) >> 10;
    int start = t * chunk;
    int end = start + chunk; if (end > N) end = N; if (start > N) start = N;
    int s = 0;
    for (int i = start; i < end; i++) s += g_deg[i];
    ps[t] = s;
    __syncthreads();
    for (int off = 1; off < 1024; off <<= 1) {
        int v = (t >= off) ? ps[t - off] : 0;
        __syncthreads();
        ps[t] += v;
        __syncthreads();
    }
    int run = ps[t] - s;                 // exclusive prefix
    for (int i = start; i < end; i++) { g_rowptr[i] = run; run += g_deg[i]; }
    if (t == 1023) g_rowptr[N] = ps[1023];
}

__global__ void scatter_kernel(const int* __restrict__ ei, int E, int N) {
    int e = blockIdx.x * blockDim.x + threadIdx.x;
    if (e < E) {
        int dst = edge_dst(ei, E, e);
        int src = edge_src(ei, E, e);
        if ((unsigned)dst >= (unsigned)N) return;
        int pos = g_rowptr[dst] + atomicAdd(&g_cur[dst], 1);
        if ((unsigned)pos < (unsigned)EMAX) g_csrc[pos] = src;
    }
}

// ---------------- GEMM + fused attention logits epilogue ----------------
// H[N,64] = X[N,K] @ W[K,64]; then es/ed computed from the block-resident tile.
template <int K, int HEADS>
__global__ __launch_bounds__(128)
void gemm_att_kernel(const float* __restrict__ X, const float* __restrict__ W,
                     float* __restrict__ H,
                     const float* __restrict__ as, const float* __restrict__ ad,
                     float* __restrict__ es, float* __restrict__ ed, int N)
{
    constexpr int KT = 64;
    __shared__ __align__(16) float xs[32][KT];     // 8 KB (reused for output tile)
    __shared__ u64 ws2[KT / 2][64];                // 16 KB: (W[k],W[k+1]) per col
    const int n0   = blockIdx.x * 32;
    const int cb   = threadIdx.x & 31;             // cols cb and cb+32
    const int slot = threadIdx.x >> 5;             // 4 slots x 8 nodes

    u64 accA[8], accB[8];
#pragma unroll
    for (int j = 0; j < 8; j++) { accA[j] = 0ull; accB[j] = 0ull; }

    for (int k0 = 0; k0 < K; k0 += KT) {
        const int len = (K - k0 < KT) ? (K - k0) : KT;   // 64 or 44; len/2 always even
        for (int i = threadIdx.x; i < 32 * len; i += 128) {
            int r = i / len, c = i - r * len;
            int n = n0 + r;
            xs[r][c] = (n < N) ? X[(size_t)n * K + k0 + c] : 0.f;
        }
        for (int i = threadIdx.x; i < (len / 2) * 64; i += 128) {
            int kk2 = i >> 6, c = i & 63;
            float w0 = W[(size_t)(k0 + 2 * kk2) * 64 + c];
            float w1 = W[(size_t)(k0 + 2 * kk2 + 1) * 64 + c];
            ws2[kk2][c] = pack2(w0, w1);
        }
        __syncthreads();
        const int len2 = len >> 1;
        for (int kk2 = 0; kk2 < len2; kk2 += 2) {
            u64 wA0 = ws2[kk2][cb],     wB0 = ws2[kk2][cb + 32];
            u64 wA1 = ws2[kk2 + 1][cb], wB1 = ws2[kk2 + 1][cb + 32];
#pragma unroll
            for (int j = 0; j < 8; j++) {
                ulonglong2 xv = *reinterpret_cast<const ulonglong2*>(&xs[slot * 8 + j][kk2 * 2]);
                accA[j] = ffma2(xv.x, wA0, accA[j]);
                accB[j] = ffma2(xv.x, wB0, accB[j]);
                accA[j] = ffma2(xv.y, wA1, accA[j]);
                accB[j] = ffma2(xv.y, wB1, accB[j]);
            }
        }
        __syncthreads();
    }

    // stage the 32x64 output tile back into xs, write H
#pragma unroll
    for (int j = 0; j < 8; j++) {
        int r = slot * 8 + j;
        int n = n0 + r;
        float a0, a1, b0, b1;
        unpack2(accA[j], a0, a1);
        unpack2(accB[j], b0, b1);
        float vA = a0 + a1, vB = b0 + b1;
        xs[r][cb] = vA; xs[r][cb + 32] = vB;
        if (n < N) {
            H[(size_t)n * 64 + cb]      = vA;
            H[(size_t)n * 64 + cb + 32] = vB;
        }
    }
    __syncthreads();

    // attention logits from shared tile
    if (HEADS == 8) {
        for (int p = threadIdx.x; p < 256; p += 128) {
            int r = p >> 3, hh = p & 7;
            int n = n0 + r;
            if (n < N) {
                float s = 0.f, d = 0.f;
#pragma unroll
                for (int k = 0; k < 8; k++) {
                    float v = xs[r][hh * 8 + k];
                    s += v * as[hh * 8 + k];
                    d += v * ad[hh * 8 + k];
                }
                es[n * 8 + hh] = s;
                ed[n * 8 + hh] = d;
            }
        }
    } else {
        int r = threadIdx.x >> 2, part = threadIdx.x & 3;
        float s = 0.f, d = 0.f;
#pragma unroll
        for (int k = 0; k < 16; k++) {
            float v = xs[r][part * 16 + k];
            s += v * as[part * 16 + k];
            d += v * ad[part * 16 + k];
        }
        s += __shfl_xor_sync(0xffffffffu, s, 1);
        s += __shfl_xor_sync(0xffffffffu, s, 2);
        d += __shfl_xor_sync(0xffffffffu, d, 1);
        d += __shfl_xor_sync(0xffffffffu, d, 2);
        int n = n0 + r;
        if (part == 0 && n < N) { es[n] = s; ed[n] = d; }
    }
}

// ---------------- layer-1 aggregation: fused softmax + gather + bias + ELU ----------------
// warp per node; lane covers cols (lane, lane+32) -> heads (lane>>3, lane>>3+4)
// edge loop unrolled x4 with loads hoisted (per-warp MLP ~16)
__global__ void agg1_kernel(const float* __restrict__ H, const float* __restrict__ bias,
                            float* __restrict__ O, int N)
{
    int g = blockIdx.x * blockDim.x + threadIdx.x;
    int n = g >> 5, lane = g & 31;
    if (n >= N) return;
    int hA = lane >> 3, hB = hA + 4;
    float edA = g_ed1[n * 8 + hA], edB = g_ed1[n * 8 + hB];

    // self-loop (PyG default add_self_loops)
    float wA = __expf(lrelu(g_es1[n * 8 + hA] + edA));
    float wB = __expf(lrelu(g_es1[n * 8 + hB] + edB));
    float wsA = wA, wsB = wB;
    float accA = wA * H[n * 64 + lane];
    float accB = wB * H[n * 64 + lane + 32];

    int e  = g_rowptr[n], e1 = g_rowptr[n + 1];
    for (; e + 4 <= e1; e += 4) {
        int s0 = g_csrc[e], s1 = g_csrc[e + 1], s2 = g_csrc[e + 2], s3 = g_csrc[e + 3];
        float a0 = g_es1[s0 * 8 + hA], c0 = g_es1[s0 * 8 + hB];
        float a1 = g_es1[s1 * 8 + hA], c1 = g_es1[s1 * 8 + hB];
        float a2 = g_es1[s2 * 8 + hA], c2 = g_es1[s2 * 8 + hB];
        float a3 = g_es1[s3 * 8 + hA], c3 = g_es1[s3 * 8 + hB];
        float hA0 = H[s0 * 64 + lane], hB0 = H[s0 * 64 + lane + 32];
        float hA1 = H[s1 * 64 + lane], hB1 = H[s1 * 64 + lane + 32];
        float hA2 = H[s2 * 64 + lane], hB2 = H[s2 * 64 + lane + 32];
        float hA3 = H[s3 * 64 + lane], hB3 = H[s3 * 64 + lane + 32];
        float x0 = __expf(lrelu(a0 + edA)), y0 = __expf(lrelu(c0 + edB));
        float x1 = __expf(lrelu(a1 + edA)), y1 = __expf(lrelu(c1 + edB));
        float x2 = __expf(lrelu(a2 + edA)), y2 = __expf(lrelu(c2 + edB));
        float x3 = __expf(lrelu(a3 + edA)), y3 = __expf(lrelu(c3 + edB));
        wsA += (x0 + x1) + (x2 + x3);
        wsB += (y0 + y1) + (y2 + y3);
        accA = fmaf(x0, hA0, accA); accA = fmaf(x1, hA1, accA);
        accA = fmaf(x2, hA2, accA); accA = fmaf(x3, hA3, accA);
        accB = fmaf(y0, hB0, accB); accB = fmaf(y1, hB1, accB);
        accB = fmaf(y2, hB2, accB); accB = fmaf(y3, hB3, accB);
    }
    for (; e < e1; e++) {
        int s = g_csrc[e];
        float xA = __expf(lrelu(g_es1[s * 8 + hA] + edA));
        float xB = __expf(lrelu(g_es1[s * 8 + hB] + edB));
        wsA += xA; wsB += xB;
        accA = fmaf(xA, H[s * 64 + lane],      accA);
        accB = fmaf(xB, H[s * 64 + lane + 32], accB);
    }
    float oA = accA / wsA + bias[lane];
    float oB = accB / wsB + bias[lane + 32];
    O[n * 64 + lane]      = oA > 0.f ? oA : (__expf(oA) - 1.f);  // ELU
    O[n * 64 + lane + 32] = oB > 0.f ? oB : (__expf(oB) - 1.f);
}

// ---------------- layer-2 aggregation + bias + log_softmax -> d_out ----------------
__global__ void agg2_kernel(const float* __restrict__ H, const float* __restrict__ bias,
                            float* __restrict__ O, int N)
{
    int g = blockIdx.x * blockDim.x + threadIdx.x;
    int n = g >> 5, lane = g & 31;
    if (n >= N) return;
    float edn = g_ed2[n];

    float w  = __expf(lrelu(g_es2[n] + edn));   // self-loop
    float ws = w;
    float accA = w * H[n * 64 + lane];
    float accB = w * H[n * 64 + lane + 32];

    int e  = g_rowptr[n], e1 = g_rowptr[n + 1];
    for (; e + 4 <= e1; e += 4) {
        int s0 = g_csrc[e], s1 = g_csrc[e + 1], s2 = g_csrc[e + 2], s3 = g_csrc[e + 3];
        float a0 = g_es2[s0], a1 = g_es2[s1], a2 = g_es2[s2], a3 = g_es2[s3];
        float hA0 = H[s0 * 64 + lane], hB0 = H[s0 * 64 + lane + 32];
        float hA1 = H[s1 * 64 + lane], hB1 = H[s1 * 64 + lane + 32];
        float hA2 = H[s2 * 64 + lane], hB2 = H[s2 * 64 + lane + 32];
        float hA3 = H[s3 * 64 + lane], hB3 = H[s3 * 64 + lane + 32];
        float x0 = __expf(lrelu(a0 + edn));
        float x1 = __expf(lrelu(a1 + edn));
        float x2 = __expf(lrelu(a2 + edn));
        float x3 = __expf(lrelu(a3 + edn));
        ws += (x0 + x1) + (x2 + x3);
        accA = fmaf(x0, hA0, accA); accA = fmaf(x1, hA1, accA);
        accA = fmaf(x2, hA2, accA); accA = fmaf(x3, hA3, accA);
        accB = fmaf(x0, hB0, accB); accB = fmaf(x1, hB1, accB);
        accB = fmaf(x2, hB2, accB); accB = fmaf(x3, hB3, accB);
    }
    for (; e < e1; e++) {
        int s = g_csrc[e];
        float x = __expf(lrelu(g_es2[s] + edn));
        ws += x;
        accA = fmaf(x, H[s * 64 + lane],      accA);
        accB = fmaf(x, H[s * 64 + lane + 32], accB);
    }
    float vA = accA / ws + bias[lane];
    float vB = accB / ws + bias[lane + 32];

    // log_softmax over 64 columns (2 per lane)
    float mx = fmaxf(vA, vB);
#pragma unroll
    for (int o = 16; o; o >>= 1) mx = fmaxf(mx, __shfl_xor_sync(0xffffffffu, mx, o));
    float se = __expf(vA - mx) + __expf(vB - mx);
#pragma unroll
    for (int o = 16; o; o >>= 1) se += __shfl_xor_sync(0xffffffffu, se, o);
    float lse = mx + logf(se);
    O[n * 64 + lane]      = vA - lse;
    O[n * 64 + lane + 32] = vB - lse;
}

// ---------------- launch ----------------
// Launch order keeps agg1 at index 5 so ncu (-s 5 -c 1) captures it next round:
// init(0) count(1) scan(2) scatter(3) gemm_att1(4) agg1(5) gemm_att2(6) agg2(7)
extern "C" void kernel_launch(void* const* d_in, const int* in_sizes, int n_in,
                              void* d_out, int out_size)
{
    const float* x   = (const float*)d_in[0];
    const int*   ei  = (const int*)d_in[1];    // int32 OR int64 (probed on device)
    const float* W1  = (const float*)d_in[2];
    const float* as1 = (const float*)d_in[3];
    const float* ad1 = (const float*)d_in[4];
    const float* b1  = (const float*)d_in[5];
    const float* W2  = (const float*)d_in[6];
    const float* as2 = (const float*)d_in[7];
    const float* ad2 = (const float*)d_in[8];
    const float* b2  = (const float*)d_in[9];

    const int N = in_sizes[0] / 300;
    const int E = in_sizes[1] / 2;
    float* out = (float*)d_out;

    void *ph1, *ph1o, *ph2, *pes1, *ped1, *pes2, *ped2;
    cudaGetSymbolAddress(&ph1,  g_h1);
    cudaGetSymbolAddress(&ph1o, g_h1o);
    cudaGetSymbolAddress(&ph2,  g_h2);
    cudaGetSymbolAddress(&pes1, g_es1);
    cudaGetSymbolAddress(&ped1, g_ed1);
    cudaGetSymbolAddress(&pes2, g_es2);
    cudaGetSymbolAddress(&ped2, g_ed2);
    float* h1  = (float*)ph1;
    float* h1o = (float*)ph1o;
    float* h2  = (float*)ph2;

    const int tb = 256;

    // CSR build (dst buckets), reused by both layers
    init_kernel   <<<(N + tb - 1) / tb, tb>>>(ei, N);
    count_kernel  <<<(E + tb - 1) / tb, tb>>>(ei, E, N);
    scan_kernel   <<<1, 1024>>>(N);
    scatter_kernel<<<(E + tb - 1) / tb, tb>>>(ei, E, N);

    // layer 1
    gemm_att_kernel<300, 8><<<(N + 31) / 32, 128>>>(x, W1, h1, as1, ad1,
                                                    (float*)pes1, (float*)ped1, N);
    agg1_kernel<<<(N + 7) / 8, tb>>>(h1, b1, h1o, N);

    // layer 2
    gemm_att_kernel<64, 1><<<(N + 31) / 32, 128>>>(h1o, W2, h2, as2, ad2,
                                                   (float*)pes2, (float*)ped2, N);
    agg2_kernel<<<(N + 7) / 8, tb>>>(h2, b2, out, N);
}

// round 9
// speedup vs baseline: 1.1375x; 1.0938x over previous
#include <cuda_runtime.h>

#define NMAX 100000
#define EMAX 1600000

// ---------------- scratch (device globals: no allocs allowed) ----------------
__device__ float g_h1 [NMAX * 64];
__device__ float g_h1o[NMAX * 64];
__device__ float g_h2 [NMAX * 64];
__device__ float g_es1[NMAX * 8];
__device__ float g_ed1[NMAX * 8];
__device__ float g_es2[NMAX];
__device__ float g_ed2[NMAX];
__device__ int   g_deg[NMAX];
__device__ int   g_cur[NMAX];
__device__ int   g_rowptr[NMAX + 1];
__device__ int   g_csrc[EMAX];
__device__ int   g_is64;

typedef unsigned long long u64;

__device__ __forceinline__ u64 pack2(float lo, float hi) {
    u64 r; asm("mov.b64 %0, {%1, %2};" : "=l"(r) : "f"(lo), "f"(hi)); return r;
}
__device__ __forceinline__ void unpack2(u64 v, float& lo, float& hi) {
    asm("mov.b64 {%0, %1}, %2;" : "=f"(lo), "=f"(hi) : "l"(v));
}
__device__ __forceinline__ u64 ffma2(u64 a, u64 b, u64 c) {
    u64 d; asm("fma.rn.f32x2 %0, %1, %2, %3;" : "=l"(d) : "l"(a), "l"(b), "l"(c)); return d;
}
__device__ __forceinline__ float lrelu(float t) { return t > 0.f ? t : 0.2f * t; }

// ---------------- init: zero deg/cur + edge dtype probe (one launch) ----------------
__global__ void init_kernel(const int* __restrict__ ei, int N) {
    int i = blockIdx.x * blockDim.x + threadIdx.x;
    if (i < N) { g_deg[i] = 0; g_cur[i] = 0; }
    if (i == 0) {
        // little-endian int64 node ids (< 2^31) have zero odd 32-bit words
        int all_zero = 1;
        for (int k = 1; k < 64; k += 2)
            if (ei[k] != 0) all_zero = 0;
        g_is64 = all_zero;
    }
}

__device__ __forceinline__ int edge_dst(const int* ei, int E, int e) {
    return g_is64 ? ei[2 * (E + e)] : ei[E + e];
}
__device__ __forceinline__ int edge_src(const int* ei, int E, int e) {
    return g_is64 ? ei[2 * e] : ei[e];
}

// ---------------- CSR build (dst-sorted), int atomics only ----------------
__global__ void count_kernel(const int* __restrict__ ei, int E, int N) {
    int e = blockIdx.x * blockDim.x + threadIdx.x;
    if (e < E) {
        int dst = edge_dst(ei, E, e);
        if ((unsigned)dst < (unsigned)N) atomicAdd(&g_deg[dst], 1);
    }
}

__global__ void scan_kernel(int N) {
    __shared__ int ps[1024];
    int t = threadIdx.x;
    int chunk = (N + 1023) >> 10;
    int start = t * chunk;
    int end = start + chunk; if (end > N) end = N; if (start > N) start = N;
    int s = 0;
    for (int i = start; i < end; i++) s += g_deg[i];
    ps[t] = s;
    __syncthreads();
    for (int off = 1; off < 1024; off <<= 1) {
        int v = (t >= off) ? ps[t - off] : 0;
        __syncthreads();
        ps[t] += v;
        __syncthreads();
    }
    int run = ps[t] - s;                 // exclusive prefix
    for (int i = start; i < end; i++) { g_rowptr[i] = run; run += g_deg[i]; }
    if (t == 1023) g_rowptr[N] = ps[1023];
}

__global__ void scatter_kernel(const int* __restrict__ ei, int E, int N) {
    int e = blockIdx.x * blockDim.x + threadIdx.x;
    if (e < E) {
        int dst = edge_dst(ei, E, e);
        int src = edge_src(ei, E, e);
        if ((unsigned)dst >= (unsigned)N) return;
        int pos = g_rowptr[dst] + atomicAdd(&g_cur[dst], 1);
        if ((unsigned)pos < (unsigned)EMAX) g_csrc[pos] = src;
    }
}

// ---------------- GEMM + fused attention logits epilogue ----------------
template <int K, int HEADS>
__global__ __launch_bounds__(128)
void gemm_att_kernel(const float* __restrict__ X, const float* __restrict__ W,
                     float* __restrict__ H,
                     const float* __restrict__ as, const float* __restrict__ ad,
                     float* __restrict__ es, float* __restrict__ ed, int N)
{
    constexpr int KT = 64;
    __shared__ __align__(16) float xs[32][KT];     // 8 KB (reused for output tile)
    __shared__ u64 ws2[KT / 2][64];                // 16 KB: (W[k],W[k+1]) per col
    const int n0   = blockIdx.x * 32;
    const int cb   = threadIdx.x & 31;             // cols cb and cb+32
    const int slot = threadIdx.x >> 5;             // 4 slots x 8 nodes

    u64 accA[8], accB[8];
#pragma unroll
    for (int j = 0; j < 8; j++) { accA[j] = 0ull; accB[j] = 0ull; }

    for (int k0 = 0; k0 < K; k0 += KT) {
        const int len = (K - k0 < KT) ? (K - k0) : KT;   // 64 or 44; len/2 always even
        for (int i = threadIdx.x; i < 32 * len; i += 128) {
            int r = i / len, c = i - r * len;
            int n = n0 + r;
            xs[r][c] = (n < N) ? X[(size_t)n * K + k0 + c] : 0.f;
        }
        for (int i = threadIdx.x; i < (len / 2) * 64; i += 128) {
            int kk2 = i >> 6, c = i & 63;
            float w0 = W[(size_t)(k0 + 2 * kk2) * 64 + c];
            float w1 = W[(size_t)(k0 + 2 * kk2 + 1) * 64 + c];
            ws2[kk2][c] = pack2(w0, w1);
        }
        __syncthreads();
        const int len2 = len >> 1;
        for (int kk2 = 0; kk2 < len2; kk2 += 2) {
            u64 wA0 = ws2[kk2][cb],     wB0 = ws2[kk2][cb + 32];
            u64 wA1 = ws2[kk2 + 1][cb], wB1 = ws2[kk2 + 1][cb + 32];
#pragma unroll
            for (int j = 0; j < 8; j++) {
                ulonglong2 xv = *reinterpret_cast<const ulonglong2*>(&xs[slot * 8 + j][kk2 * 2]);
                accA[j] = ffma2(xv.x, wA0, accA[j]);
                accB[j] = ffma2(xv.x, wB0, accB[j]);
                accA[j] = ffma2(xv.y, wA1, accA[j]);
                accB[j] = ffma2(xv.y, wB1, accB[j]);
            }
        }
        __syncthreads();
    }

    // stage the 32x64 output tile back into xs, write H
#pragma unroll
    for (int j = 0; j < 8; j++) {
        int r = slot * 8 + j;
        int n = n0 + r;
        float a0, a1, b0, b1;
        unpack2(accA[j], a0, a1);
        unpack2(accB[j], b0, b1);
        float vA = a0 + a1, vB = b0 + b1;
        xs[r][cb] = vA; xs[r][cb + 32] = vB;
        if (n < N) {
            H[(size_t)n * 64 + cb]      = vA;
            H[(size_t)n * 64 + cb + 32] = vB;
        }
    }
    __syncthreads();

    // attention logits from shared tile
    if (HEADS == 8) {
        for (int p = threadIdx.x; p < 256; p += 128) {
            int r = p >> 3, hh = p & 7;
            int n = n0 + r;
            if (n < N) {
                float s = 0.f, d = 0.f;
#pragma unroll
                for (int k = 0; k < 8; k++) {
                    float v = xs[r][hh * 8 + k];
                    s += v * as[hh * 8 + k];
                    d += v * ad[hh * 8 + k];
                }
                es[n * 8 + hh] = s;
                ed[n * 8 + hh] = d;
            }
        }
    } else {
        int r = threadIdx.x >> 2, part = threadIdx.x & 3;
        float s = 0.f, d = 0.f;
#pragma unroll
        for (int k = 0; k < 16; k++) {
            float v = xs[r][part * 16 + k];
            s += v * as[part * 16 + k];
            d += v * ad[part * 16 + k];
        }
        s += __shfl_xor_sync(0xffffffffu, s, 1);
        s += __shfl_xor_sync(0xffffffffu, s, 2);
        d += __shfl_xor_sync(0xffffffffu, d, 1);
        d += __shfl_xor_sync(0xffffffffu, d, 2);
        int n = n0 + r;
        if (part == 0 && n < N) { es[n] = s; ed[n] = d; }
    }
}

// ---------------- layer-1 aggregation (float2 lanes: 3 LDG/edge) ----------------
// warp per node; lane covers cols (2*lane, 2*lane+1) -> head lane>>2
__global__ void agg1_kernel(const float* __restrict__ H, const float* __restrict__ bias,
                            float* __restrict__ O, int N)
{
    int g = blockIdx.x * blockDim.x + threadIdx.x;
    int n = g >> 5, lane = g & 31;
    if (n >= N) return;
    const float2* __restrict__ H2 = reinterpret_cast<const float2*>(H);
    int hh = lane >> 2;
    float edv = g_ed1[n * 8 + hh];

    // self-loop (PyG default add_self_loops)
    float w = __expf(lrelu(g_es1[n * 8 + hh] + edv));
    float ws = w;
    float2 hv = H2[n * 32 + lane];
    float accx = w * hv.x, accy = w * hv.y;

    int e = g_rowptr[n], e1 = g_rowptr[n + 1];
    for (; e + 4 <= e1; e += 4) {
        int s0 = g_csrc[e], s1 = g_csrc[e + 1], s2 = g_csrc[e + 2], s3 = g_csrc[e + 3];
        float a0 = g_es1[s0 * 8 + hh], a1 = g_es1[s1 * 8 + hh];
        float a2 = g_es1[s2 * 8 + hh], a3 = g_es1[s3 * 8 + hh];
        float2 h0 = H2[s0 * 32 + lane], h1v = H2[s1 * 32 + lane];
        float2 h2v = H2[s2 * 32 + lane], h3 = H2[s3 * 32 + lane];
        float x0 = __expf(lrelu(a0 + edv));
        float x1 = __expf(lrelu(a1 + edv));
        float x2 = __expf(lrelu(a2 + edv));
        float x3 = __expf(lrelu(a3 + edv));
        ws += (x0 + x1) + (x2 + x3);
        accx = fmaf(x0, h0.x,  accx); accy = fmaf(x0, h0.y,  accy);
        accx = fmaf(x1, h1v.x, accx); accy = fmaf(x1, h1v.y, accy);
        accx = fmaf(x2, h2v.x, accx); accy = fmaf(x2, h2v.y, accy);
        accx = fmaf(x3, h3.x,  accx); accy = fmaf(x3, h3.y,  accy);
    }
    for (; e < e1; e++) {
        int s = g_csrc[e];
        float x = __expf(lrelu(g_es1[s * 8 + hh] + edv));
        float2 hv2 = H2[s * 32 + lane];
        ws += x;
        accx = fmaf(x, hv2.x, accx);
        accy = fmaf(x, hv2.y, accy);
    }
    float2 bv = reinterpret_cast<const float2*>(bias)[lane];
    float ox = accx / ws + bv.x;
    float oy = accy / ws + bv.y;
    float2 ov;
    ov.x = ox > 0.f ? ox : (__expf(ox) - 1.f);   // ELU
    ov.y = oy > 0.f ? oy : (__expf(oy) - 1.f);
    reinterpret_cast<float2*>(O)[n * 32 + lane] = ov;
}

// ---------------- layer-2 aggregation + bias + log_softmax -> d_out ----------------
__global__ void agg2_kernel(const float* __restrict__ H, const float* __restrict__ bias,
                            float* __restrict__ O, int N)
{
    int g = blockIdx.x * blockDim.x + threadIdx.x;
    int n = g >> 5, lane = g & 31;
    if (n >= N) return;
    const float2* __restrict__ H2 = reinterpret_cast<const float2*>(H);
    float edn = g_ed2[n];

    float w  = __expf(lrelu(g_es2[n] + edn));   // self-loop
    float ws = w;
    float2 hv = H2[n * 32 + lane];
    float accx = w * hv.x, accy = w * hv.y;

    int e = g_rowptr[n], e1 = g_rowptr[n + 1];
    for (; e + 4 <= e1; e += 4) {
        int s0 = g_csrc[e], s1 = g_csrc[e + 1], s2 = g_csrc[e + 2], s3 = g_csrc[e + 3];
        float a0 = g_es2[s0], a1 = g_es2[s1], a2 = g_es2[s2], a3 = g_es2[s3];
        float2 h0 = H2[s0 * 32 + lane], h1v = H2[s1 * 32 + lane];
        float2 h2v = H2[s2 * 32 + lane], h3 = H2[s3 * 32 + lane];
        float x0 = __expf(lrelu(a0 + edn));
        float x1 = __expf(lrelu(a1 + edn));
        float x2 = __expf(lrelu(a2 + edn));
        float x3 = __expf(lrelu(a3 + edn));
        ws += (x0 + x1) + (x2 + x3);
        accx = fmaf(x0, h0.x,  accx); accy = fmaf(x0, h0.y,  accy);
        accx = fmaf(x1, h1v.x, accx); accy = fmaf(x1, h1v.y, accy);
        accx = fmaf(x2, h2v.x, accx); accy = fmaf(x2, h2v.y, accy);
        accx = fmaf(x3, h3.x,  accx); accy = fmaf(x3, h3.y,  accy);
    }
    for (; e < e1; e++) {
        int s = g_csrc[e];
        float x = __expf(lrelu(g_es2[s] + edn));
        float2 hv2 = H2[s * 32 + lane];
        ws += x;
        accx = fmaf(x, hv2.x, accx);
        accy = fmaf(x, hv2.y, accy);
    }
    float2 bv = reinterpret_cast<const float2*>(bias)[lane];
    float vA = accx / ws + bv.x;
    float vB = accy / ws + bv.y;

    // log_softmax over 64 columns (2 per lane)
    float mx = fmaxf(vA, vB);
#pragma unroll
    for (int o = 16; o; o >>= 1) mx = fmaxf(mx, __shfl_xor_sync(0xffffffffu, mx, o));
    float se = __expf(vA - mx) + __expf(vB - mx);
#pragma unroll
    for (int o = 16; o; o >>= 1) se += __shfl_xor_sync(0xffffffffu, se, o);
    float lse = mx + logf(se);
    float2 ov; ov.x = vA - lse; ov.y = vB - lse;
    reinterpret_cast<float2*>(O)[n * 32 + lane] = ov;
}

// ---------------- launch ----------------
extern "C" void kernel_launch(void* const* d_in, const int* in_sizes, int n_in,
                              void* d_out, int out_size)
{
    const float* x   = (const float*)d_in[0];
    const int*   ei  = (const int*)d_in[1];    // int32 OR int64 (probed on device)
    const float* W1  = (const float*)d_in[2];
    const float* as1 = (const float*)d_in[3];
    const float* ad1 = (const float*)d_in[4];
    const float* b1  = (const float*)d_in[5];
    const float* W2  = (const float*)d_in[6];
    const float* as2 = (const float*)d_in[7];
    const float* ad2 = (const float*)d_in[8];
    const float* b2  = (const float*)d_in[9];

    const int N = in_sizes[0] / 300;
    const int E = in_sizes[1] / 2;
    float* out = (float*)d_out;

    void *ph1, *ph1o, *ph2, *pes1, *ped1, *pes2, *ped2;
    cudaGetSymbolAddress(&ph1,  g_h1);
    cudaGetSymbolAddress(&ph1o, g_h1o);
    cudaGetSymbolAddress(&ph2,  g_h2);
    cudaGetSymbolAddress(&pes1, g_es1);
    cudaGetSymbolAddress(&ped1, g_ed1);
    cudaGetSymbolAddress(&pes2, g_es2);
    cudaGetSymbolAddress(&ped2, g_ed2);
    float* h1  = (float*)ph1;
    float* h1o = (float*)ph1o;
    float* h2  = (float*)ph2;

    const int tb = 256;

    // CSR build (dst buckets), reused by both layers
    init_kernel   <<<(N + tb - 1) / tb, tb>>>(ei, N);
    count_kernel  <<<(E + tb - 1) / tb, tb>>>(ei, E, N);
    scan_kernel   <<<1, 1024>>>(N);
    scatter_kernel<<<(E + tb - 1) / tb, tb>>>(ei, E, N);

    // layer 1
    gemm_att_kernel<300, 8><<<(N + 31) / 32, 128>>>(x, W1, h1, as1, ad1,
                                                    (float*)pes1, (float*)ped1, N);
    agg1_kernel<<<(N + 7) / 8, tb>>>(h1, b1, h1o, N);

    // layer 2
    gemm_att_kernel<64, 1><<<(N + 31) / 32, 128>>>(h1o, W2, h2, as2, ad2,
                                                   (float*)pes2, (float*)ped2, N);
    agg2_kernel<<<(N + 7) / 8, tb>>>(h2, b2, out, N);
}